// round 4
// baseline (speedup 1.0000x reference)
#include <cuda_runtime.h>
#include <cstdint>

#define N_NODES 100000
#define N_EDGES 1600000
#define N_GRAPHS 512
#define D 64
#define BN_EPS 1e-5f

// ------------------------- device scratch (no allocs allowed) ---------------
__device__ __align__(16) float g_sums[(size_t)N_NODES * D];   // scatter accumulator
__device__ float g_cnt[N_NODES];
__device__ __align__(16) float g_bufA[(size_t)N_NODES * D];
__device__ __align__(16) float g_bufB[(size_t)N_NODES * D];
__device__ float g_stats[3 * 128];              // per layer: sum[64], sumsq[64]
__device__ float g_W2f[D * D];
__device__ float g_b2f[D];
__device__ float g_W3f[D * D];
__device__ float g_b3f[D];
__device__ float g_aff[128];                    // a3[64], c3[64]
__device__ int g_is64;                          // 1 if indices are int64

// ------------------------- helpers ------------------------------------------
__device__ __forceinline__ void ffma2(unsigned long long& d, unsigned long long a,
                                      unsigned long long b) {
    asm("fma.rn.f32x2 %0, %1, %2, %0;" : "+l"(d) : "l"(a), "l"(b));
}
__device__ __forceinline__ unsigned long long pack2(float v) {
    unsigned long long r;
    asm("mov.b64 %0, {%1, %1};" : "=l"(r) : "f"(v));
    return r;
}
__device__ __forceinline__ void unpack2(unsigned long long p, float& lo, float& hi) {
    asm("mov.b64 {%0, %1}, %2;" : "=f"(lo), "=f"(hi) : "l"(p));
}
// Load index i from an array that may be int32 or int64 (flag-selected).
__device__ __forceinline__ int load_idx(const void* p, int i, int is64, int lim) {
    int v;
    if (is64) v = (int)__ldg(reinterpret_cast<const long long*>(p) + i);
    else      v = __ldg(reinterpret_cast<const int*>(p) + i);
    return min(max(v, 0), lim - 1);  // defensive clamp: never fault
}

// ------------------------- zero scratch + dtype detection --------------------
__global__ void k_zero(const int* __restrict__ ei32) {
    int i = blockIdx.x * blockDim.x + threadIdx.x;   // up to 1.6M
    if (i < (N_NODES * D) / 4)
        reinterpret_cast<float4*>(g_sums)[i] = make_float4(0.f, 0.f, 0.f, 0.f);
    if (i < N_NODES) g_cnt[i] = 0.f;
    if (i < 3 * 128) g_stats[i] = 0.f;
    if (i == 0) {
        // If data is int64 (values < 2^31), odd 32-bit words are zero high-words.
        // If data is int32 random indices, odd words are nonzero w.h.p.
        int nz = 0;
        for (int k = 1; k < 64; k += 2) nz |= ei32[k];
        g_is64 = (nz == 0) ? 1 : 0;
    }
}

// ------------------------- edge scatter (segment_sum + counts) ---------------
__global__ void k_scatter(const void* __restrict__ src,
                          const float* __restrict__ ea) {
    int idx = blockIdx.x * blockDim.x + threadIdx.x;  // E*16 threads
    int e = idx >> 4;
    if (e >= N_EDGES) return;
    int q = idx & 15;
    int is64 = g_is64;
    int s = load_idx(src, e, is64, N_NODES);
    float4 v = reinterpret_cast<const float4*>(ea)[e * 16 + q];
    float* dst = g_sums + (size_t)s * D + q * 4;
    asm volatile("red.global.add.v4.f32 [%0], {%1,%2,%3,%4};"
                 :: "l"(dst), "f"(v.x), "f"(v.y), "f"(v.z), "f"(v.w) : "memory");
    if (q == 0) atomicAdd(g_cnt + s, 1.0f);
}

// ------------------------- layer 1: comb[192] @ W1 + b1, relu ----------------
// Block = 64 rows x 64 cols, 256 threads (4 threads/row, 16 cols each).
// K processed in 3 chunks of 64: x | v_e | global_attr[batch].
__global__ void k_layer1(const float* __restrict__ x,
                         const float* __restrict__ ga,
                         const void* __restrict__ batch,
                         const float* __restrict__ W1,
                         const float* __restrict__ b1,
                         float* __restrict__ out) {
    __shared__ __align__(16) float comb_s[64][68];
    __shared__ __align__(16) float W_s[64 * 64];
    __shared__ float b_s[64];
    __shared__ int batch_s[64];

    int t = threadIdx.x;
    int rowBase = blockIdx.x * 64;
    if (t < 64) {
        b_s[t] = b1[t];
        int gr = rowBase + t;
        batch_s[t] = (gr < N_NODES) ? load_idx(batch, gr, g_is64, N_GRAPHS) : 0;
    }
    int r = t >> 2, cg = t & 3;
    unsigned long long acc[8] = {0, 0, 0, 0, 0, 0, 0, 0};

    for (int c = 0; c < 3; c++) {
        __syncthreads();
        // load W1 chunk [64][64]
        for (int i = t; i < 4096; i += 256) W_s[i] = W1[c * 4096 + i];
        // load comb chunk [64 rows][64 cols] as float4
        for (int i = t; i < 1024; i += 256) {
            int rr = i >> 4, c4 = i & 15;
            int gr = rowBase + rr;
            float4 v = make_float4(0.f, 0.f, 0.f, 0.f);
            if (gr < N_NODES) {
                if (c == 0) {
                    v = reinterpret_cast<const float4*>(x)[gr * 16 + c4];
                } else if (c == 1) {
                    v = reinterpret_cast<const float4*>(g_sums)[gr * 16 + c4];
                    float inv = 1.0f / fmaxf(g_cnt[gr], 1.0f);
                    v.x *= inv; v.y *= inv; v.z *= inv; v.w *= inv;
                } else {
                    int b = batch_s[rr];
                    v = reinterpret_cast<const float4*>(ga)[b * 16 + c4];
                }
            }
            *reinterpret_cast<float4*>(&comb_s[rr][c4 * 4]) = v;
        }
        __syncthreads();
#pragma unroll 8
        for (int kk = 0; kk < 64; kk++) {
            unsigned long long cc = pack2(comb_s[r][kk]);
            const ulonglong2* w =
                reinterpret_cast<const ulonglong2*>(W_s + kk * 64 + cg * 16);
            ulonglong2 w0 = w[0], w1 = w[1], w2 = w[2], w3 = w[3];
            ffma2(acc[0], cc, w0.x); ffma2(acc[1], cc, w0.y);
            ffma2(acc[2], cc, w1.x); ffma2(acc[3], cc, w1.y);
            ffma2(acc[4], cc, w2.x); ffma2(acc[5], cc, w2.y);
            ffma2(acc[6], cc, w3.x); ffma2(acc[7], cc, w3.y);
        }
    }

    int gr = rowBase + r;
    if (gr < N_NODES) {
        float res[16];
#pragma unroll
        for (int i = 0; i < 8; i++) unpack2(acc[i], res[2 * i], res[2 * i + 1]);
#pragma unroll
        for (int i = 0; i < 16; i++)
            res[i] = fmaxf(res[i] + b_s[cg * 16 + i], 0.f);
        float4* o = reinterpret_cast<float4*>(out + (size_t)gr * D + cg * 16);
        o[0] = make_float4(res[0], res[1], res[2], res[3]);
        o[1] = make_float4(res[4], res[5], res[6], res[7]);
        o[2] = make_float4(res[8], res[9], res[10], res[11]);
        o[3] = make_float4(res[12], res[13], res[14], res[15]);
    }
}

// ------------------------- layers 2/3: in[64] @ Wf + bf, relu ----------------
__global__ void k_layer64(const float* __restrict__ in,
                          const float* __restrict__ Wf,
                          const float* __restrict__ bf,
                          float* __restrict__ out) {
    __shared__ __align__(16) float in_s[64][68];
    __shared__ __align__(16) float W_s[64 * 64];
    __shared__ float b_s[64];

    int t = threadIdx.x;
    int rowBase = blockIdx.x * 64;
    for (int i = t; i < 4096; i += 256) W_s[i] = Wf[i];
    if (t < 64) b_s[t] = bf[t];
    for (int i = t; i < 1024; i += 256) {
        int rr = i >> 4, c4 = i & 15;
        int gr = rowBase + rr;
        float4 v = (gr < N_NODES)
                       ? reinterpret_cast<const float4*>(in)[gr * 16 + c4]
                       : make_float4(0.f, 0.f, 0.f, 0.f);
        *reinterpret_cast<float4*>(&in_s[rr][c4 * 4]) = v;
    }
    __syncthreads();

    int r = t >> 2, cg = t & 3;
    unsigned long long acc[8] = {0, 0, 0, 0, 0, 0, 0, 0};
#pragma unroll 8
    for (int kk = 0; kk < 64; kk++) {
        unsigned long long cc = pack2(in_s[r][kk]);
        const ulonglong2* w =
            reinterpret_cast<const ulonglong2*>(W_s + kk * 64 + cg * 16);
        ulonglong2 w0 = w[0], w1 = w[1], w2 = w[2], w3 = w[3];
        ffma2(acc[0], cc, w0.x); ffma2(acc[1], cc, w0.y);
        ffma2(acc[2], cc, w1.x); ffma2(acc[3], cc, w1.y);
        ffma2(acc[4], cc, w2.x); ffma2(acc[5], cc, w2.y);
        ffma2(acc[6], cc, w3.x); ffma2(acc[7], cc, w3.y);
    }

    int gr = rowBase + r;
    if (gr < N_NODES) {
        float res[16];
#pragma unroll
        for (int i = 0; i < 8; i++) unpack2(acc[i], res[2 * i], res[2 * i + 1]);
#pragma unroll
        for (int i = 0; i < 16; i++)
            res[i] = fmaxf(res[i] + b_s[cg * 16 + i], 0.f);
        float4* o = reinterpret_cast<float4*>(out + (size_t)gr * D + cg * 16);
        o[0] = make_float4(res[0], res[1], res[2], res[3]);
        o[1] = make_float4(res[4], res[5], res[6], res[7]);
        o[2] = make_float4(res[8], res[9], res[10], res[11]);
        o[3] = make_float4(res[12], res[13], res[14], res[15]);
    }
}

// ------------------------- column stats (sum, sumsq) -------------------------
__global__ void k_stats(const float* __restrict__ h, float* __restrict__ st) {
    int col = threadIdx.x & 63;
    int sub = threadIdx.x >> 6;  // 0..3
    float s = 0.f, s2 = 0.f;
    for (int row = blockIdx.x * 4 + sub; row < N_NODES; row += gridDim.x * 4) {
        float v = h[(size_t)row * D + col];
        s += v;
        s2 += v * v;
    }
    __shared__ float sh[2][4][64];
    sh[0][sub][col] = s;
    sh[1][sub][col] = s2;
    __syncthreads();
    if (threadIdx.x < 64) {
        float a = sh[0][0][col] + sh[0][1][col] + sh[0][2][col] + sh[0][3][col];
        atomicAdd(st + col, a);
    } else if (threadIdx.x < 128) {
        float a = sh[1][0][col] + sh[1][1][col] + sh[1][2][col] + sh[1][3][col];
        atomicAdd(st + 64 + col, a);
    }
}

// ------------------------- fold BN into next layer's weights -----------------
__global__ void k_fold(const float* __restrict__ st, const float* __restrict__ g,
                       const float* __restrict__ bt, const float* __restrict__ W,
                       const float* __restrict__ b, float* __restrict__ Wf,
                       float* __restrict__ bf) {
    __shared__ float a_s[64], c_s[64];
    int t = threadIdx.x;
    const float invN = 1.0f / (float)N_NODES;
    if (t < 64) {
        float mean = st[t] * invN;
        float var = st[64 + t] * invN - mean * mean;
        float a = g[t] * rsqrtf(var + BN_EPS);
        a_s[t] = a;
        c_s[t] = bt[t] - mean * a;
    }
    __syncthreads();
    for (int i = t; i < 4096; i += 256) {
        int k = i >> 6;
        Wf[i] = a_s[k] * W[i];
    }
    if (t < 64) {
        float acc = b[t];
        for (int k = 0; k < 64; k++) acc += c_s[k] * W[k * 64 + t];
        bf[t] = acc;
    }
}

// ------------------------- final BN as per-column affine ---------------------
__global__ void k_fold3(const float* __restrict__ st, const float* __restrict__ g,
                        const float* __restrict__ bt, float* __restrict__ aff) {
    int t = threadIdx.x;
    const float invN = 1.0f / (float)N_NODES;
    if (t < 64) {
        float mean = st[t] * invN;
        float var = st[64 + t] * invN - mean * mean;
        float a = g[t] * rsqrtf(var + BN_EPS);
        aff[t] = a;
        aff[64 + t] = bt[t] - mean * a;
    }
}

__global__ void k_final(const float* __restrict__ h, const float* __restrict__ aff,
                        float* __restrict__ out) {
    int i = blockIdx.x * blockDim.x + threadIdx.x;  // float4 index
    if (i >= N_NODES * 16) return;
    int c4 = i & 15;
    float4 v = reinterpret_cast<const float4*>(h)[i];
    float4 a = reinterpret_cast<const float4*>(aff)[c4];
    float4 c = reinterpret_cast<const float4*>(aff)[16 + c4];
    v.x = v.x * a.x + c.x;
    v.y = v.y * a.y + c.y;
    v.z = v.z * a.z + c.z;
    v.w = v.w * a.w + c.w;
    reinterpret_cast<float4*>(out)[i] = v;
}

// ------------------------- launch -------------------------------------------
extern "C" void kernel_launch(void* const* d_in, const int* in_sizes, int n_in,
                              void* d_out, int out_size) {
    const float* x = (const float*)d_in[0];
    const void* ei = d_in[1];          // int32 or int64 — detected on device
    const float* ea = (const float*)d_in[2];
    const float* ga = (const float*)d_in[3];
    const void* batch = d_in[4];       // int32 or int64 — detected on device
    const float* W1 = (const float*)d_in[5];
    const float* b1 = (const float*)d_in[6];
    const float* W2 = (const float*)d_in[7];
    const float* b2 = (const float*)d_in[8];
    const float* W3 = (const float*)d_in[9];
    const float* b3 = (const float*)d_in[10];
    const float* g1 = (const float*)d_in[11];
    const float* bt1 = (const float*)d_in[12];
    const float* g2 = (const float*)d_in[13];
    const float* bt2 = (const float*)d_in[14];
    const float* g3 = (const float*)d_in[15];
    const float* bt3 = (const float*)d_in[16];
    float* out = (float*)d_out;

    float *pA, *pB, *pStats, *pW2f, *pb2f, *pW3f, *pb3f, *pAff;
    cudaGetSymbolAddress((void**)&pA, g_bufA);
    cudaGetSymbolAddress((void**)&pB, g_bufB);
    cudaGetSymbolAddress((void**)&pStats, g_stats);
    cudaGetSymbolAddress((void**)&pW2f, g_W2f);
    cudaGetSymbolAddress((void**)&pb2f, g_b2f);
    cudaGetSymbolAddress((void**)&pW3f, g_W3f);
    cudaGetSymbolAddress((void**)&pb3f, g_b3f);
    cudaGetSymbolAddress((void**)&pAff, g_aff);

    const int rowBlocks = (N_NODES + 63) / 64;  // 1563

    k_zero<<<(N_NODES * D / 4 + 255) / 256, 256>>>((const int*)ei);
    k_scatter<<<(N_EDGES * 16) / 256, 256>>>(ei, ea);
    k_layer1<<<rowBlocks, 256>>>(x, ga, batch, W1, b1, pA);
    k_stats<<<592, 256>>>(pA, pStats);
    k_fold<<<1, 256>>>(pStats, g1, bt1, W2, b2, pW2f, pb2f);
    k_layer64<<<rowBlocks, 256>>>(pA, pW2f, pb2f, pB);
    k_stats<<<592, 256>>>(pB, pStats + 128);
    k_fold<<<1, 256>>>(pStats + 128, g2, bt2, W3, b3, pW3f, pb3f);
    k_layer64<<<rowBlocks, 256>>>(pB, pW3f, pb3f, pA);
    k_stats<<<592, 256>>>(pA, pStats + 256);
    k_fold3<<<1, 64>>>(pStats + 256, g3, bt3, pAff);
    k_final<<<(N_NODES * 16 + 255) / 256, 256>>>(pA, pAff, out);
}

// round 5
// speedup vs baseline: 1.5071x; 1.5071x over previous
#include <cuda_runtime.h>
#include <cstdint>

#define N_NODES 100000
#define N_EDGES 1600000
#define N_GRAPHS 512
#define D 64
#define BN_EPS 1e-5f

// ------------------------- device scratch (no allocs allowed) ---------------
__device__ __align__(16) float g_sums[(size_t)N_NODES * D];   // scatter accumulator
__device__ float g_cnt[N_NODES];
__device__ __align__(16) float g_bufA[(size_t)N_NODES * D];
__device__ __align__(16) float g_bufB[(size_t)N_NODES * D];
__device__ float g_stats[3 * 128];              // per layer: sum[64], sumsq[64]
__device__ float g_W2f[D * D];
__device__ float g_b2f[D];
__device__ float g_W3f[D * D];
__device__ float g_b3f[D];
__device__ float g_aff[128];                    // a3[64], c3[64]
__device__ int g_is64;                          // 1 if indices are int64

// ------------------------- helpers ------------------------------------------
__device__ __forceinline__ void ffma2(unsigned long long& d, unsigned long long a,
                                      unsigned long long b) {
    asm("fma.rn.f32x2 %0, %1, %2, %0;" : "+l"(d) : "l"(a), "l"(b));
}
__device__ __forceinline__ unsigned long long pack2(float v) {
    unsigned long long r;
    asm("mov.b64 %0, {%1, %1};" : "=l"(r) : "f"(v));
    return r;
}
__device__ __forceinline__ void unpack2(unsigned long long p, float& lo, float& hi) {
    asm("mov.b64 {%0, %1}, %2;" : "=f"(lo), "=f"(hi) : "l"(p));
}
// Load index i from an array that may be int32 or int64 (flag-selected).
__device__ __forceinline__ int load_idx(const void* p, int i, int is64, int lim) {
    int v;
    if (is64) v = (int)__ldg(reinterpret_cast<const long long*>(p) + i);
    else      v = __ldg(reinterpret_cast<const int*>(p) + i);
    return min(max(v, 0), lim - 1);  // defensive clamp: never fault
}

// ------------------------- zero scratch + dtype detection --------------------
__global__ void k_zero(const int* __restrict__ ei32) {
    int i = blockIdx.x * blockDim.x + threadIdx.x;   // up to 1.6M
    if (i < (N_NODES * D) / 4)
        reinterpret_cast<float4*>(g_sums)[i] = make_float4(0.f, 0.f, 0.f, 0.f);
    if (i < N_NODES) g_cnt[i] = 0.f;
    if (i < 3 * 128) g_stats[i] = 0.f;
    if (i == 0) {
        // If data is int64 (values < 2^31), odd 32-bit words are zero high-words.
        // If data is int32 random indices, odd words are nonzero w.h.p.
        int nz = 0;
        for (int k = 1; k < 64; k += 2) nz |= ei32[k];
        g_is64 = (nz == 0) ? 1 : 0;
    }
}

// ------------------------- edge scatter (segment_sum + counts) ---------------
__global__ void k_scatter(const void* __restrict__ src,
                          const float* __restrict__ ea) {
    int idx = blockIdx.x * blockDim.x + threadIdx.x;  // E*16 threads
    int e = idx >> 4;
    if (e >= N_EDGES) return;
    int q = idx & 15;
    int is64 = g_is64;
    int s = load_idx(src, e, is64, N_NODES);
    float4 v = reinterpret_cast<const float4*>(ea)[e * 16 + q];
    float* dst = g_sums + (size_t)s * D + q * 4;
    asm volatile("red.global.add.v4.f32 [%0], {%1,%2,%3,%4};"
                 :: "l"(dst), "f"(v.x), "f"(v.y), "f"(v.z), "f"(v.w) : "memory");
    if (q == 0) atomicAdd(g_cnt + s, 1.0f);
}

// ===================== shared epilogue: relu + stats + store ================
// Each thread holds acc0/acc1 (rows g0,g1; 16 cols at cg*16). Reduces column
// sum/sumsq across the block via shfl + smem, atomically adds to st[128].
__device__ __forceinline__ void epilogue_store_stats(
    unsigned long long* acc0, unsigned long long* acc1,
    const float* b_s, float (*red_s)[2][64],
    int t, int cg, int g0, int g1,
    float* __restrict__ out, float* __restrict__ st) {

    float res0[16], res1[16];
#pragma unroll
    for (int i = 0; i < 8; i++) {
        unpack2(acc0[i], res0[2 * i], res0[2 * i + 1]);
        unpack2(acc1[i], res1[2 * i], res1[2 * i + 1]);
    }
    bool v0 = g0 < N_NODES, v1 = g1 < N_NODES;
    float s[16], s2[16];
#pragma unroll
    for (int i = 0; i < 16; i++) {
        float b = b_s[cg * 16 + i];
        res0[i] = fmaxf(res0[i] + b, 0.f);
        res1[i] = fmaxf(res1[i] + b, 0.f);
        float a0 = v0 ? res0[i] : 0.f;
        float a1 = v1 ? res1[i] : 0.f;
        s[i] = a0 + a1;
        s2[i] = a0 * a0 + a1 * a1;
    }
    // reduce over the 8 row-groups within the warp (lanes xor 4,8,16)
#pragma unroll
    for (int m = 4; m <= 16; m <<= 1) {
#pragma unroll
        for (int i = 0; i < 16; i++) {
            s[i] += __shfl_xor_sync(0xffffffffu, s[i], m);
            s2[i] += __shfl_xor_sync(0xffffffffu, s2[i], m);
        }
    }
    int warp = t >> 5, lane = t & 31;
    if (lane < 4) {
#pragma unroll
        for (int i = 0; i < 16; i++) {
            red_s[warp][0][lane * 16 + i] = s[i];
            red_s[warp][1][lane * 16 + i] = s2[i];
        }
    }
    if (v0) {
        float4* o = reinterpret_cast<float4*>(out + (size_t)g0 * D + cg * 16);
        o[0] = make_float4(res0[0], res0[1], res0[2], res0[3]);
        o[1] = make_float4(res0[4], res0[5], res0[6], res0[7]);
        o[2] = make_float4(res0[8], res0[9], res0[10], res0[11]);
        o[3] = make_float4(res0[12], res0[13], res0[14], res0[15]);
    }
    if (v1) {
        float4* o = reinterpret_cast<float4*>(out + (size_t)g1 * D + cg * 16);
        o[0] = make_float4(res1[0], res1[1], res1[2], res1[3]);
        o[1] = make_float4(res1[4], res1[5], res1[6], res1[7]);
        o[2] = make_float4(res1[8], res1[9], res1[10], res1[11]);
        o[3] = make_float4(res1[12], res1[13], res1[14], res1[15]);
    }
    __syncthreads();
    if (t < 128) {
        int which = t >> 6, col = t & 63;
        float a = 0.f;
#pragma unroll
        for (int w = 0; w < 8; w++) a += red_s[w][which][col];
        atomicAdd(st + which * 64 + col, a);
    }
}

// ------------------------- layer 1: comb[192] @ W1 + b1, relu + stats --------
// Block = 128 rows x 64 cols, 256 threads (2 rows x 16 cols per thread).
// K processed in 6 half-chunks of 32; sources: x | v_e | global_attr[batch].
__global__ __launch_bounds__(256) void k_layer1(
        const float* __restrict__ x,
        const float* __restrict__ ga,
        const void* __restrict__ batch,
        const float* __restrict__ W1,
        const float* __restrict__ b1,
        float* __restrict__ out,
        float* __restrict__ st) {
    __shared__ __align__(16) float in_s[128][68];
    __shared__ __align__(16) float W_s[32 * 64];
    __shared__ float red_s[8][2][64];
    __shared__ float b_s[64];
    __shared__ int batch_s[128];

    int t = threadIdx.x;
    int rowBase = blockIdx.x * 128;
    if (t < 64) b_s[t] = b1[t];
    if (t < 128) {
        int gr = rowBase + t;
        batch_s[t] = (gr < N_NODES) ? load_idx(batch, gr, g_is64, N_GRAPHS) : 0;
    }
    int rg = t >> 2, cg = t & 3;
    int r0 = rg * 2, r1 = rg * 2 + 1;
    unsigned long long acc0[8] = {0, 0, 0, 0, 0, 0, 0, 0};
    unsigned long long acc1[8] = {0, 0, 0, 0, 0, 0, 0, 0};

    for (int h = 0; h < 6; h++) {
        int c = h >> 1;
        __syncthreads();
        if ((h & 1) == 0) {
            // load in_s [128][64] from source c
            for (int i = t; i < 2048; i += 256) {
                int rr = i >> 4, c4 = i & 15;
                int gr = rowBase + rr;
                float4 v = make_float4(0.f, 0.f, 0.f, 0.f);
                if (gr < N_NODES) {
                    if (c == 0) {
                        v = reinterpret_cast<const float4*>(x)[gr * 16 + c4];
                    } else if (c == 1) {
                        v = reinterpret_cast<const float4*>(g_sums)[gr * 16 + c4];
                        float inv = 1.0f / fmaxf(g_cnt[gr], 1.0f);
                        v.x *= inv; v.y *= inv; v.z *= inv; v.w *= inv;
                    } else {
                        v = reinterpret_cast<const float4*>(ga)[batch_s[rr] * 16 + c4];
                    }
                }
                *reinterpret_cast<float4*>(&in_s[rr][c4 * 4]) = v;
            }
        }
        // load W half-chunk: global k rows h*32 .. h*32+31
        for (int i = t; i < 2048; i += 256) W_s[i] = W1[h * 2048 + i];
        __syncthreads();
        int kb = (h & 1) * 32;
#pragma unroll
        for (int kk = 0; kk < 32; kk++) {
            unsigned long long ca = pack2(in_s[r0][kb + kk]);
            unsigned long long cb = pack2(in_s[r1][kb + kk]);
            const ulonglong2* w =
                reinterpret_cast<const ulonglong2*>(W_s + kk * 64 + cg * 16);
            ulonglong2 w0 = w[0], w1 = w[1], w2 = w[2], w3 = w[3];
            ffma2(acc0[0], ca, w0.x); ffma2(acc0[1], ca, w0.y);
            ffma2(acc0[2], ca, w1.x); ffma2(acc0[3], ca, w1.y);
            ffma2(acc0[4], ca, w2.x); ffma2(acc0[5], ca, w2.y);
            ffma2(acc0[6], ca, w3.x); ffma2(acc0[7], ca, w3.y);
            ffma2(acc1[0], cb, w0.x); ffma2(acc1[1], cb, w0.y);
            ffma2(acc1[2], cb, w1.x); ffma2(acc1[3], cb, w1.y);
            ffma2(acc1[4], cb, w2.x); ffma2(acc1[5], cb, w2.y);
            ffma2(acc1[6], cb, w3.x); ffma2(acc1[7], cb, w3.y);
        }
    }
    __syncthreads();
    epilogue_store_stats(acc0, acc1, b_s, red_s, t, cg,
                         rowBase + r0, rowBase + r1, out, st);
}

// ------------------------- layers 2/3: in[64] @ Wf + bf, relu + stats --------
__global__ __launch_bounds__(256) void k_layer64(
        const float* __restrict__ in,
        const float* __restrict__ Wf,
        const float* __restrict__ bf,
        float* __restrict__ out,
        float* __restrict__ st) {
    __shared__ __align__(16) float in_s[128][68];
    __shared__ __align__(16) float W_s[32 * 64];
    __shared__ float red_s[8][2][64];
    __shared__ float b_s[64];

    int t = threadIdx.x;
    int rowBase = blockIdx.x * 128;
    if (t < 64) b_s[t] = bf[t];
    for (int i = t; i < 2048; i += 256) {
        int rr = i >> 4, c4 = i & 15;
        int gr = rowBase + rr;
        float4 v = (gr < N_NODES)
                       ? reinterpret_cast<const float4*>(in)[gr * 16 + c4]
                       : make_float4(0.f, 0.f, 0.f, 0.f);
        *reinterpret_cast<float4*>(&in_s[rr][c4 * 4]) = v;
    }

    int rg = t >> 2, cg = t & 3;
    int r0 = rg * 2, r1 = rg * 2 + 1;
    unsigned long long acc0[8] = {0, 0, 0, 0, 0, 0, 0, 0};
    unsigned long long acc1[8] = {0, 0, 0, 0, 0, 0, 0, 0};

    for (int h = 0; h < 2; h++) {
        __syncthreads();
        for (int i = t; i < 2048; i += 256) W_s[i] = Wf[h * 2048 + i];
        __syncthreads();
        int kb = h * 32;
#pragma unroll
        for (int kk = 0; kk < 32; kk++) {
            unsigned long long ca = pack2(in_s[r0][kb + kk]);
            unsigned long long cb = pack2(in_s[r1][kb + kk]);
            const ulonglong2* w =
                reinterpret_cast<const ulonglong2*>(W_s + kk * 64 + cg * 16);
            ulonglong2 w0 = w[0], w1 = w[1], w2 = w[2], w3 = w[3];
            ffma2(acc0[0], ca, w0.x); ffma2(acc0[1], ca, w0.y);
            ffma2(acc0[2], ca, w1.x); ffma2(acc0[3], ca, w1.y);
            ffma2(acc0[4], ca, w2.x); ffma2(acc0[5], ca, w2.y);
            ffma2(acc0[6], ca, w3.x); ffma2(acc0[7], ca, w3.y);
            ffma2(acc1[0], cb, w0.x); ffma2(acc1[1], cb, w0.y);
            ffma2(acc1[2], cb, w1.x); ffma2(acc1[3], cb, w1.y);
            ffma2(acc1[4], cb, w2.x); ffma2(acc1[5], cb, w2.y);
            ffma2(acc1[6], cb, w3.x); ffma2(acc1[7], cb, w3.y);
        }
    }
    __syncthreads();
    epilogue_store_stats(acc0, acc1, b_s, red_s, t, cg,
                         rowBase + r0, rowBase + r1, out, st);
}

// ------------------------- fold BN into next layer's weights -----------------
__global__ void k_fold(const float* __restrict__ st, const float* __restrict__ g,
                       const float* __restrict__ bt, const float* __restrict__ W,
                       const float* __restrict__ b, float* __restrict__ Wf,
                       float* __restrict__ bf) {
    __shared__ float a_s[64], c_s[64];
    int t = threadIdx.x;
    const float invN = 1.0f / (float)N_NODES;
    if (t < 64) {
        float mean = st[t] * invN;
        float var = st[64 + t] * invN - mean * mean;
        float a = g[t] * rsqrtf(var + BN_EPS);
        a_s[t] = a;
        c_s[t] = bt[t] - mean * a;
    }
    __syncthreads();
    for (int i = t; i < 4096; i += 256) {
        int k = i >> 6;
        Wf[i] = a_s[k] * W[i];
    }
    if (t < 64) {
        float acc = b[t];
        for (int k = 0; k < 64; k++) acc += c_s[k] * W[k * 64 + t];
        bf[t] = acc;
    }
}

// ------------------------- final BN as per-column affine ---------------------
__global__ void k_fold3(const float* __restrict__ st, const float* __restrict__ g,
                        const float* __restrict__ bt, float* __restrict__ aff) {
    int t = threadIdx.x;
    const float invN = 1.0f / (float)N_NODES;
    if (t < 64) {
        float mean = st[t] * invN;
        float var = st[64 + t] * invN - mean * mean;
        float a = g[t] * rsqrtf(var + BN_EPS);
        aff[t] = a;
        aff[64 + t] = bt[t] - mean * a;
    }
}

__global__ void k_final(const float* __restrict__ h, const float* __restrict__ aff,
                        float* __restrict__ out) {
    int i = blockIdx.x * blockDim.x + threadIdx.x;  // float4 index
    if (i >= N_NODES * 16) return;
    int c4 = i & 15;
    float4 v = reinterpret_cast<const float4*>(h)[i];
    float4 a = reinterpret_cast<const float4*>(aff)[c4];
    float4 c = reinterpret_cast<const float4*>(aff)[16 + c4];
    v.x = v.x * a.x + c.x;
    v.y = v.y * a.y + c.y;
    v.z = v.z * a.z + c.z;
    v.w = v.w * a.w + c.w;
    reinterpret_cast<float4*>(out)[i] = v;
}

// ------------------------- launch -------------------------------------------
extern "C" void kernel_launch(void* const* d_in, const int* in_sizes, int n_in,
                              void* d_out, int out_size) {
    const float* x = (const float*)d_in[0];
    const void* ei = d_in[1];          // int32 or int64 — detected on device
    const float* ea = (const float*)d_in[2];
    const float* ga = (const float*)d_in[3];
    const void* batch = d_in[4];       // int32 or int64 — detected on device
    const float* W1 = (const float*)d_in[5];
    const float* b1 = (const float*)d_in[6];
    const float* W2 = (const float*)d_in[7];
    const float* b2 = (const float*)d_in[8];
    const float* W3 = (const float*)d_in[9];
    const float* b3 = (const float*)d_in[10];
    const float* g1 = (const float*)d_in[11];
    const float* bt1 = (const float*)d_in[12];
    const float* g2 = (const float*)d_in[13];
    const float* bt2 = (const float*)d_in[14];
    const float* g3 = (const float*)d_in[15];
    const float* bt3 = (const float*)d_in[16];
    float* out = (float*)d_out;

    float *pA, *pB, *pStats, *pW2f, *pb2f, *pW3f, *pb3f, *pAff;
    cudaGetSymbolAddress((void**)&pA, g_bufA);
    cudaGetSymbolAddress((void**)&pB, g_bufB);
    cudaGetSymbolAddress((void**)&pStats, g_stats);
    cudaGetSymbolAddress((void**)&pW2f, g_W2f);
    cudaGetSymbolAddress((void**)&pb2f, g_b2f);
    cudaGetSymbolAddress((void**)&pW3f, g_W3f);
    cudaGetSymbolAddress((void**)&pb3f, g_b3f);
    cudaGetSymbolAddress((void**)&pAff, g_aff);

    const int rowBlocks = (N_NODES + 127) / 128;  // 782

    k_zero<<<(N_NODES * D / 4 + 255) / 256, 256>>>((const int*)ei);
    k_scatter<<<(N_EDGES * 16) / 256, 256>>>(ei, ea);
    k_layer1<<<rowBlocks, 256>>>(x, ga, batch, W1, b1, pA, pStats);
    k_fold<<<1, 256>>>(pStats, g1, bt1, W2, b2, pW2f, pb2f);
    k_layer64<<<rowBlocks, 256>>>(pA, pW2f, pb2f, pB, pStats + 128);
    k_fold<<<1, 256>>>(pStats + 128, g2, bt2, W3, b3, pW3f, pb3f);
    k_layer64<<<rowBlocks, 256>>>(pB, pW3f, pb3f, pA, pStats + 256);
    k_fold3<<<1, 64>>>(pStats + 256, g3, bt3, pAff);
    k_final<<<(N_NODES * 16 + 255) / 256, 256>>>(pA, pAff, out);
}

// round 7
// speedup vs baseline: 1.5518x; 1.0296x over previous
#include <cuda_runtime.h>
#include <cstdint>

#define N_NODES 100000
#define N_EDGES 1600000
#define N_GRAPHS 512
#define D 64
#define BN_EPS 1e-5f

// ------------------------- device scratch (no allocs allowed) ---------------
__device__ __align__(16) float g_sums[(size_t)N_NODES * D];   // scatter accumulator
__device__ float g_cnt[N_NODES];
__device__ __align__(16) float g_bufA[(size_t)N_NODES * D];
__device__ __align__(16) float g_bufB[(size_t)N_NODES * D];
__device__ float g_stats[3 * 128];              // per layer: sum[64], sumsq[64]
__device__ int g_is64;                          // 1 if indices are int64

// ------------------------- helpers ------------------------------------------
__device__ __forceinline__ void ffma2(unsigned long long& d, unsigned long long a,
                                      unsigned long long b) {
    asm("fma.rn.f32x2 %0, %1, %2, %0;" : "+l"(d) : "l"(a), "l"(b));
}
__device__ __forceinline__ unsigned long long pack2(float v) {
    unsigned long long r;
    asm("mov.b64 %0, {%1, %1};" : "=l"(r) : "f"(v));
    return r;
}
__device__ __forceinline__ void unpack2(unsigned long long p, float& lo, float& hi) {
    asm("mov.b64 {%0, %1}, %2;" : "=f"(lo), "=f"(hi) : "l"(p));
}
// Load index i from an array that may be int32 or int64 (flag-selected).
__device__ __forceinline__ int load_idx(const void* p, int i, int is64, int lim) {
    int v;
    if (is64) v = (int)__ldg(reinterpret_cast<const long long*>(p) + i);
    else      v = __ldg(reinterpret_cast<const int*>(p) + i);
    return min(max(v, 0), lim - 1);  // defensive clamp: never fault
}

// ------------------------- zero scratch (split so scatter = launch #6) -------
__global__ void k_zeroA() {   // g_sums first half: 800K float4
    int i = blockIdx.x * blockDim.x + threadIdx.x;
    reinterpret_cast<float4*>(g_sums)[i] = make_float4(0.f, 0.f, 0.f, 0.f);
}
__global__ void k_zeroB() {   // g_sums second half
    int i = blockIdx.x * blockDim.x + threadIdx.x;
    reinterpret_cast<float4*>(g_sums)[800000 + i] = make_float4(0.f, 0.f, 0.f, 0.f);
}
__global__ void k_zeroC1() {  // g_cnt first half
    int i = blockIdx.x * blockDim.x + threadIdx.x;
    if (i < 50000) g_cnt[i] = 0.f;
}
__global__ void k_zeroC2() {  // g_cnt second half
    int i = blockIdx.x * blockDim.x + threadIdx.x;
    if (i < 50000) g_cnt[50000 + i] = 0.f;
}
__global__ void k_zeroD(const int* __restrict__ ei32) {  // stats + dtype detect
    int i = threadIdx.x;
    if (i < 3 * 128) g_stats[i] = 0.f;
    if (i == 0) {
        // int64 data (values < 2^31) -> odd 32-bit words are zero high-words.
        int nz = 0;
        for (int k = 1; k < 64; k += 2) nz |= ei32[k];
        g_is64 = (nz == 0) ? 1 : 0;
    }
}

// ------------------------- edge scatter (segment_sum + counts) ---------------
__global__ void k_scatter(const void* __restrict__ src,
                          const float* __restrict__ ea) {
    int idx = blockIdx.x * blockDim.x + threadIdx.x;  // E*16 threads
    int e = idx >> 4;
    if (e >= N_EDGES) return;
    int q = idx & 15;
    int is64 = g_is64;
    int s = load_idx(src, e, is64, N_NODES);
    float4 v = reinterpret_cast<const float4*>(ea)[e * 16 + q];
    float* dst = g_sums + (size_t)s * D + q * 4;
    asm volatile("red.global.add.v4.f32 [%0], {%1,%2,%3,%4};"
                 :: "l"(dst), "f"(v.x), "f"(v.y), "f"(v.z), "f"(v.w) : "memory");
    if (q == 0)
        asm volatile("red.global.add.f32 [%0], %1;"
                     :: "l"(g_cnt + s), "f"(1.0f) : "memory");
}

// ===================== shared epilogue: relu + stats + store ================
__device__ __forceinline__ void epilogue_store_stats(
    unsigned long long* acc0, unsigned long long* acc1,
    const float* b_s, float (*red_s)[2][64],
    int t, int cg, int g0, int g1,
    float* __restrict__ out, float* __restrict__ st) {

    float res0[16], res1[16];
#pragma unroll
    for (int i = 0; i < 8; i++) {
        unpack2(acc0[i], res0[2 * i], res0[2 * i + 1]);
        unpack2(acc1[i], res1[2 * i], res1[2 * i + 1]);
    }
    bool v0 = g0 < N_NODES, v1 = g1 < N_NODES;
    float s[16], s2[16];
#pragma unroll
    for (int i = 0; i < 16; i++) {
        float b = b_s[cg * 16 + i];
        res0[i] = fmaxf(res0[i] + b, 0.f);
        res1[i] = fmaxf(res1[i] + b, 0.f);
        float a0 = v0 ? res0[i] : 0.f;
        float a1 = v1 ? res1[i] : 0.f;
        s[i] = a0 + a1;
        s2[i] = a0 * a0 + a1 * a1;
    }
#pragma unroll
    for (int m = 4; m <= 16; m <<= 1) {
#pragma unroll
        for (int i = 0; i < 16; i++) {
            s[i] += __shfl_xor_sync(0xffffffffu, s[i], m);
            s2[i] += __shfl_xor_sync(0xffffffffu, s2[i], m);
        }
    }
    int warp = t >> 5, lane = t & 31;
    if (lane < 4) {
#pragma unroll
        for (int i = 0; i < 16; i++) {
            red_s[warp][0][lane * 16 + i] = s[i];
            red_s[warp][1][lane * 16 + i] = s2[i];
        }
    }
    if (v0) {
        float4* o = reinterpret_cast<float4*>(out + (size_t)g0 * D + cg * 16);
        o[0] = make_float4(res0[0], res0[1], res0[2], res0[3]);
        o[1] = make_float4(res0[4], res0[5], res0[6], res0[7]);
        o[2] = make_float4(res0[8], res0[9], res0[10], res0[11]);
        o[3] = make_float4(res0[12], res0[13], res0[14], res0[15]);
    }
    if (v1) {
        float4* o = reinterpret_cast<float4*>(out + (size_t)g1 * D + cg * 16);
        o[0] = make_float4(res1[0], res1[1], res1[2], res1[3]);
        o[1] = make_float4(res1[4], res1[5], res1[6], res1[7]);
        o[2] = make_float4(res1[8], res1[9], res1[10], res1[11]);
        o[3] = make_float4(res1[12], res1[13], res1[14], res1[15]);
    }
    __syncthreads();
    if (t < 128) {
        int which = t >> 6, col = t & 63;
        float a = 0.f;
#pragma unroll
        for (int w = 0; w < 8; w++) a += red_s[w][which][col];
        atomicAdd(st + which * 64 + col, a);
    }
}

// ------------------------- layer 1: comb[192] @ W1 + b1, relu + stats --------
__global__ __launch_bounds__(256) void k_layer1(
        const float* __restrict__ x,
        const float* __restrict__ ga,
        const void* __restrict__ batch,
        const float* __restrict__ W1,
        const float* __restrict__ b1,
        float* __restrict__ out,
        float* __restrict__ st) {
    __shared__ __align__(16) float in_s[128][68];
    __shared__ __align__(16) float W_s[32 * 64];
    __shared__ float red_s[8][2][64];
    __shared__ float b_s[64];
    __shared__ int batch_s[128];

    int t = threadIdx.x;
    int rowBase = blockIdx.x * 128;
    if (t < 64) b_s[t] = b1[t];
    if (t < 128) {
        int gr = rowBase + t;
        batch_s[t] = (gr < N_NODES) ? load_idx(batch, gr, g_is64, N_GRAPHS) : 0;
    }
    int rg = t >> 2, cg = t & 3;
    int r0 = rg * 2, r1 = rg * 2 + 1;
    unsigned long long acc0[8] = {0, 0, 0, 0, 0, 0, 0, 0};
    unsigned long long acc1[8] = {0, 0, 0, 0, 0, 0, 0, 0};

    for (int h = 0; h < 6; h++) {
        int c = h >> 1;
        __syncthreads();
        if ((h & 1) == 0) {
            for (int i = t; i < 2048; i += 256) {
                int rr = i >> 4, c4 = i & 15;
                int gr = rowBase + rr;
                float4 v = make_float4(0.f, 0.f, 0.f, 0.f);
                if (gr < N_NODES) {
                    if (c == 0) {
                        v = reinterpret_cast<const float4*>(x)[gr * 16 + c4];
                    } else if (c == 1) {
                        v = reinterpret_cast<const float4*>(g_sums)[gr * 16 + c4];
                        float inv = 1.0f / fmaxf(g_cnt[gr], 1.0f);
                        v.x *= inv; v.y *= inv; v.z *= inv; v.w *= inv;
                    } else {
                        v = reinterpret_cast<const float4*>(ga)[batch_s[rr] * 16 + c4];
                    }
                }
                *reinterpret_cast<float4*>(&in_s[rr][c4 * 4]) = v;
            }
        }
        // load W half-chunk (float4): global k rows h*32 .. h*32+31
        for (int i = t; i < 512; i += 256)
            reinterpret_cast<float4*>(W_s)[i] =
                reinterpret_cast<const float4*>(W1 + h * 2048)[i];
        __syncthreads();
        int kb = (h & 1) * 32;
#pragma unroll
        for (int kk = 0; kk < 32; kk++) {
            unsigned long long ca = pack2(in_s[r0][kb + kk]);
            unsigned long long cb = pack2(in_s[r1][kb + kk]);
            const ulonglong2* w =
                reinterpret_cast<const ulonglong2*>(W_s + kk * 64 + cg * 16);
            ulonglong2 w0 = w[0], w1 = w[1], w2 = w[2], w3 = w[3];
            ffma2(acc0[0], ca, w0.x); ffma2(acc0[1], ca, w0.y);
            ffma2(acc0[2], ca, w1.x); ffma2(acc0[3], ca, w1.y);
            ffma2(acc0[4], ca, w2.x); ffma2(acc0[5], ca, w2.y);
            ffma2(acc0[6], ca, w3.x); ffma2(acc0[7], ca, w3.y);
            ffma2(acc1[0], cb, w0.x); ffma2(acc1[1], cb, w0.y);
            ffma2(acc1[2], cb, w1.x); ffma2(acc1[3], cb, w1.y);
            ffma2(acc1[4], cb, w2.x); ffma2(acc1[5], cb, w2.y);
            ffma2(acc1[6], cb, w3.x); ffma2(acc1[7], cb, w3.y);
        }
    }
    __syncthreads();
    epilogue_store_stats(acc0, acc1, b_s, red_s, t, cg,
                         rowBase + r0, rowBase + r1, out, st);
}

// --------- layers 2/3: BN(prev stats) folded into W on the fly, relu + stats -
__global__ __launch_bounds__(256) void k_layer64(
        const float* __restrict__ in,
        const float* __restrict__ W,      // raw weights [64][64]
        const float* __restrict__ b,      // raw bias
        const float* __restrict__ st,     // prev-layer stats (sum, sumsq)
        const float* __restrict__ g,      // prev-layer BN gamma
        const float* __restrict__ bt,     // prev-layer BN beta
        float* __restrict__ out,
        float* __restrict__ st_out) {
    __shared__ __align__(16) float in_s[128][68];
    __shared__ __align__(16) float W_s[32 * 64];
    __shared__ float red_s[8][2][64];
    __shared__ float a_s[64], c_s[64], b_s[64];
    __shared__ float bred[4][64];

    int t = threadIdx.x;
    int rowBase = blockIdx.x * 128;

    // stage 0: BN fold coefficients from prev-layer stats
    if (t < 64) {
        const float invN = 1.0f / (float)N_NODES;
        float mean = st[t] * invN;
        float var = st[64 + t] * invN - mean * mean;
        float a = g[t] * rsqrtf(var + BN_EPS);
        a_s[t] = a;
        c_s[t] = bt[t] - mean * a;
    }
    __syncthreads();

    // stage 1: in_s loads + folded-bias partials
    for (int i = t; i < 2048; i += 256) {
        int rr = i >> 4, c4 = i & 15;
        int gr = rowBase + rr;
        float4 v = (gr < N_NODES)
                       ? reinterpret_cast<const float4*>(in)[gr * 16 + c4]
                       : make_float4(0.f, 0.f, 0.f, 0.f);
        *reinterpret_cast<float4*>(&in_s[rr][c4 * 4]) = v;
    }
    {
        int q = t >> 6, col = t & 63;
        float acc = 0.f;
#pragma unroll
        for (int kk = 0; kk < 16; kk++) {
            int k = q * 16 + kk;
            acc += c_s[k] * __ldg(W + k * 64 + col);
        }
        bred[q][col] = acc;
    }
    __syncthreads();
    if (t < 64) b_s[t] = b[t] + bred[0][t] + bred[1][t] + bred[2][t] + bred[3][t];

    int rg = t >> 2, cg = t & 3;
    int r0 = rg * 2, r1 = rg * 2 + 1;
    unsigned long long acc0[8] = {0, 0, 0, 0, 0, 0, 0, 0};
    unsigned long long acc1[8] = {0, 0, 0, 0, 0, 0, 0, 0};

    for (int h = 0; h < 2; h++) {
        __syncthreads();
        // load W half-chunk, scaled by a_s[k] (float4 along columns: same k)
        for (int i = t; i < 512; i += 256) {
            int k = h * 32 + (i >> 4);
            float4 w = reinterpret_cast<const float4*>(W + h * 2048)[i];
            float a = a_s[k];
            w.x *= a; w.y *= a; w.z *= a; w.w *= a;
            reinterpret_cast<float4*>(W_s)[i] = w;
        }
        __syncthreads();
        int kb = h * 32;
#pragma unroll
        for (int kk = 0; kk < 32; kk++) {
            unsigned long long ca = pack2(in_s[r0][kb + kk]);
            unsigned long long cb = pack2(in_s[r1][kb + kk]);
            const ulonglong2* w =
                reinterpret_cast<const ulonglong2*>(W_s + kk * 64 + cg * 16);
            ulonglong2 w0 = w[0], w1 = w[1], w2 = w[2], w3 = w[3];
            ffma2(acc0[0], ca, w0.x); ffma2(acc0[1], ca, w0.y);
            ffma2(acc0[2], ca, w1.x); ffma2(acc0[3], ca, w1.y);
            ffma2(acc0[4], ca, w2.x); ffma2(acc0[5], ca, w2.y);
            ffma2(acc0[6], ca, w3.x); ffma2(acc0[7], ca, w3.y);
            ffma2(acc1[0], cb, w0.x); ffma2(acc1[1], cb, w0.y);
            ffma2(acc1[2], cb, w1.x); ffma2(acc1[3], cb, w1.y);
            ffma2(acc1[4], cb, w2.x); ffma2(acc1[5], cb, w2.y);
            ffma2(acc1[6], cb, w3.x); ffma2(acc1[7], cb, w3.y);
        }
    }
    __syncthreads();
    epilogue_store_stats(acc0, acc1, b_s, red_s, t, cg,
                         rowBase + r0, rowBase + r1, out, st_out);
}

// -------------- final: BN(stats3) applied as per-column affine ---------------
__global__ __launch_bounds__(256) void k_final(
        const float* __restrict__ h, const float* __restrict__ st,
        const float* __restrict__ g, const float* __restrict__ bt,
        float* __restrict__ out) {
    __shared__ float a_s[64], c_s[64];
    int t = threadIdx.x;
    if (t < 64) {
        const float invN = 1.0f / (float)N_NODES;
        float mean = st[t] * invN;
        float var = st[64 + t] * invN - mean * mean;
        float a = g[t] * rsqrtf(var + BN_EPS);
        a_s[t] = a;
        c_s[t] = bt[t] - mean * a;
    }
    __syncthreads();
    int i = blockIdx.x * blockDim.x + t;  // float4 index
    if (i >= N_NODES * 16) return;
    int c4 = (i & 15) * 4;
    float4 v = reinterpret_cast<const float4*>(h)[i];
    v.x = v.x * a_s[c4 + 0] + c_s[c4 + 0];
    v.y = v.y * a_s[c4 + 1] + c_s[c4 + 1];
    v.z = v.z * a_s[c4 + 2] + c_s[c4 + 2];
    v.w = v.w * a_s[c4 + 3] + c_s[c4 + 3];
    reinterpret_cast<float4*>(out)[i] = v;
}

// ------------------------- launch -------------------------------------------
extern "C" void kernel_launch(void* const* d_in, const int* in_sizes, int n_in,
                              void* d_out, int out_size) {
    const float* x = (const float*)d_in[0];
    const void* ei = d_in[1];          // int32 or int64 — detected on device
    const float* ea = (const float*)d_in[2];
    const float* ga = (const float*)d_in[3];
    const void* batch = d_in[4];       // int32 or int64 — detected on device
    const float* W1 = (const float*)d_in[5];
    const float* b1 = (const float*)d_in[6];
    const float* W2 = (const float*)d_in[7];
    const float* b2 = (const float*)d_in[8];
    const float* W3 = (const float*)d_in[9];
    const float* b3 = (const float*)d_in[10];
    const float* g1 = (const float*)d_in[11];
    const float* bt1 = (const float*)d_in[12];
    const float* g2 = (const float*)d_in[13];
    const float* bt2 = (const float*)d_in[14];
    const float* g3 = (const float*)d_in[15];
    const float* bt3 = (const float*)d_in[16];
    float* out = (float*)d_out;

    float *pA, *pB, *pStats;
    cudaGetSymbolAddress((void**)&pA, g_bufA);
    cudaGetSymbolAddress((void**)&pB, g_bufB);
    cudaGetSymbolAddress((void**)&pStats, g_stats);

    const int rowBlocks = (N_NODES + 127) / 128;  // 782

    // launches 0..4 (tiny) so that k_scatter is launch #6 (ncu -s 5 -c 1)
    k_zeroA<<<3125, 256>>>();
    k_zeroB<<<3125, 256>>>();
    k_zeroC1<<<196, 256>>>();
    k_zeroC2<<<196, 256>>>();
    k_zeroD<<<1, 384>>>((const int*)ei);
    k_scatter<<<(N_EDGES * 16) / 256, 256>>>(ei, ea);
    k_layer1<<<rowBlocks, 256>>>(x, ga, batch, W1, b1, pA, pStats);
    k_layer64<<<rowBlocks, 256>>>(pA, W2, b2, pStats, g1, bt1, pB, pStats + 128);
    k_layer64<<<rowBlocks, 256>>>(pB, W3, b3, pStats + 128, g2, bt2, pA, pStats + 256);
    k_final<<<(N_NODES * 16 + 255) / 256, 256>>>(pA, pStats + 256, g3, bt3, out);
}

// round 10
// speedup vs baseline: 2.2376x; 1.4419x over previous
#include <cuda_runtime.h>
#include <cstdint>

#define N_NODES 100000
#define N_EDGES 1600000
#define N_GRAPHS 512
#define D 64
#define BN_EPS 1e-5f
#define NREP 16   // stats replicas to de-serialize atomics

// ------------------------- device scratch (no allocs allowed) ---------------
__device__ __align__(16) float g_sums[(size_t)N_NODES * D];   // scatter accumulator
__device__ float g_cnt[N_NODES];
__device__ __align__(16) float g_bufA[(size_t)N_NODES * D];
__device__ __align__(16) float g_bufB[(size_t)N_NODES * D];
__device__ float g_stats[3 * NREP * 128];       // [layer][replica][sum64|sumsq64]
__device__ int g_is64;                          // 1 if indices are int64

// ------------------------- helpers ------------------------------------------
__device__ __forceinline__ void ffma2(unsigned long long& d, unsigned long long a,
                                      unsigned long long b) {
    asm("fma.rn.f32x2 %0, %1, %2, %0;" : "+l"(d) : "l"(a), "l"(b));
}
__device__ __forceinline__ unsigned long long pack2(float v) {
    unsigned long long r;
    asm("mov.b64 %0, {%1, %1};" : "=l"(r) : "f"(v));
    return r;
}
__device__ __forceinline__ void unpack2(unsigned long long p, float& lo, float& hi) {
    asm("mov.b64 {%0, %1}, %2;" : "=f"(lo), "=f"(hi) : "l"(p));
}
// Load index i from an array that may be int32 or int64 (flag-selected).
__device__ __forceinline__ int load_idx(const void* p, int i, int is64, int lim) {
    int v;
    if (is64) v = (int)__ldg(reinterpret_cast<const long long*>(p) + i);
    else      v = __ldg(reinterpret_cast<const int*>(p) + i);
    return min(max(v, 0), lim - 1);  // defensive clamp: never fault
}

// --------------- zero scratch (3 launches so scatter = launch #4) ------------
__global__ void k_zero1() {   // g_sums: 1.6M float4
    int i = blockIdx.x * blockDim.x + threadIdx.x;
    reinterpret_cast<float4*>(g_sums)[i] = make_float4(0.f, 0.f, 0.f, 0.f);
}
__global__ void k_zero2() {   // g_cnt
    int i = blockIdx.x * blockDim.x + threadIdx.x;
    if (i < N_NODES) g_cnt[i] = 0.f;
}
__global__ void k_zero3(const int* __restrict__ ei32) {  // stats + dtype detect
    int t = threadIdx.x;
    for (int i = t; i < 3 * NREP * 128; i += 256) g_stats[i] = 0.f;
    if (t == 0) {
        // int64 data (values < 2^31) -> odd 32-bit words are zero high-words.
        int nz = 0;
        for (int k = 1; k < 64; k += 2) nz |= ei32[k];
        g_is64 = (nz == 0) ? 1 : 0;
    }
}

// ------------------------- edge scatter (segment_sum + counts) ---------------
__global__ void k_scatter(const void* __restrict__ src,
                          const float* __restrict__ ea) {
    int idx = blockIdx.x * blockDim.x + threadIdx.x;  // E*16 threads
    int e = idx >> 4;
    if (e >= N_EDGES) return;
    int q = idx & 15;
    int is64 = g_is64;
    int s = load_idx(src, e, is64, N_NODES);
    float4 v = reinterpret_cast<const float4*>(ea)[e * 16 + q];
    float* dst = g_sums + (size_t)s * D + q * 4;
    asm volatile("red.global.add.v4.f32 [%0], {%1,%2,%3,%4};"
                 :: "l"(dst), "f"(v.x), "f"(v.y), "f"(v.z), "f"(v.w) : "memory");
    if (q == 0)
        asm volatile("red.global.add.f32 [%0], %1;"
                     :: "l"(g_cnt + s), "f"(1.0f) : "memory");
}

// ===================== shared epilogue: relu + stats + store ================
// Thread holds rows g0,g1 and 16 cols: col(i) = cg*4 + (i>>2)*16 + (i&3).
__device__ __forceinline__ void epilogue_store_stats(
    unsigned long long* acc0, unsigned long long* acc1,
    const float* b_s, float (*red_s)[2][64],
    int t, int cg, int g0, int g1, int rep,
    float* __restrict__ out, float* __restrict__ st) {

    float res0[16], res1[16];
#pragma unroll
    for (int i = 0; i < 8; i++) {
        unpack2(acc0[i], res0[2 * i], res0[2 * i + 1]);
        unpack2(acc1[i], res1[2 * i], res1[2 * i + 1]);
    }
    bool v0 = g0 < N_NODES, v1 = g1 < N_NODES;
    float s[16], s2[16];
#pragma unroll
    for (int i = 0; i < 16; i++) {
        int col = cg * 4 + ((i >> 2) << 4) + (i & 3);
        float b = b_s[col];
        res0[i] = fmaxf(res0[i] + b, 0.f);
        res1[i] = fmaxf(res1[i] + b, 0.f);
        float a0 = v0 ? res0[i] : 0.f;
        float a1 = v1 ? res1[i] : 0.f;
        s[i] = a0 + a1;
        s2[i] = a0 * a0 + a1 * a1;
    }
#pragma unroll
    for (int m = 4; m <= 16; m <<= 1) {
#pragma unroll
        for (int i = 0; i < 16; i++) {
            s[i] += __shfl_xor_sync(0xffffffffu, s[i], m);
            s2[i] += __shfl_xor_sync(0xffffffffu, s2[i], m);
        }
    }
    int warp = t >> 5, lane = t & 31;
    if (lane < 4) {
#pragma unroll
        for (int i = 0; i < 16; i++) {
            int col = lane * 4 + ((i >> 2) << 4) + (i & 3);
            red_s[warp][0][col] = s[i];
            red_s[warp][1][col] = s2[i];
        }
    }
    if (v0) {
        float4* o = reinterpret_cast<float4*>(out + (size_t)g0 * D);
#pragma unroll
        for (int j = 0; j < 4; j++)
            o[cg + j * 4] = make_float4(res0[j * 4], res0[j * 4 + 1],
                                        res0[j * 4 + 2], res0[j * 4 + 3]);
    }
    if (v1) {
        float4* o = reinterpret_cast<float4*>(out + (size_t)g1 * D);
#pragma unroll
        for (int j = 0; j < 4; j++)
            o[cg + j * 4] = make_float4(res1[j * 4], res1[j * 4 + 1],
                                        res1[j * 4 + 2], res1[j * 4 + 3]);
    }
    __syncthreads();
    if (t < 128) {
        int which = t >> 6, col = t & 63;
        float a = 0.f;
#pragma unroll
        for (int w = 0; w < 8; w++) a += red_s[w][which][col];
        atomicAdd(st + rep * 128 + which * 64 + col, a);
    }
}

// ------------------------- GEMM inner chunk (32 k-steps) --------------------
__device__ __forceinline__ void mma_chunk(
    const float (*in_s)[68], const float* W_s, int r0, int r1, int cg, int kb,
    unsigned long long* acc0, unsigned long long* acc1) {
#pragma unroll
    for (int kk = 0; kk < 32; kk++) {
        unsigned long long ca = pack2(in_s[r0][kb + kk]);
        unsigned long long cb = pack2(in_s[r1][kb + kk]);
        const ulonglong2* wrow = reinterpret_cast<const ulonglong2*>(W_s + kk * 64);
        ulonglong2 w0 = wrow[cg], w1 = wrow[cg + 4];
        ulonglong2 w2 = wrow[cg + 8], w3 = wrow[cg + 12];
        ffma2(acc0[0], ca, w0.x); ffma2(acc0[1], ca, w0.y);
        ffma2(acc0[2], ca, w1.x); ffma2(acc0[3], ca, w1.y);
        ffma2(acc0[4], ca, w2.x); ffma2(acc0[5], ca, w2.y);
        ffma2(acc0[6], ca, w3.x); ffma2(acc0[7], ca, w3.y);
        ffma2(acc1[0], cb, w0.x); ffma2(acc1[1], cb, w0.y);
        ffma2(acc1[2], cb, w1.x); ffma2(acc1[3], cb, w1.y);
        ffma2(acc1[4], cb, w2.x); ffma2(acc1[5], cb, w2.y);
        ffma2(acc1[6], cb, w3.x); ffma2(acc1[7], cb, w3.y);
    }
}

// ------------------------- layer 1: comb[192] @ W1 + b1, relu + stats --------
__global__ __launch_bounds__(256) void k_layer1(
        const float* __restrict__ x,
        const float* __restrict__ ga,
        const void* __restrict__ batch,
        const float* __restrict__ W1,
        const float* __restrict__ b1,
        float* __restrict__ out,
        float* __restrict__ st) {
    __shared__ __align__(16) float in_s[128][68];
    __shared__ __align__(16) float W_s[32 * 64];
    __shared__ float red_s[8][2][64];
    __shared__ float b_s[64];
    __shared__ int batch_s[128];

    int t = threadIdx.x;
    int rowBase = blockIdx.x * 128;
    if (t < 64) b_s[t] = b1[t];
    if (t < 128) {
        int gr = rowBase + t;
        batch_s[t] = (gr < N_NODES) ? load_idx(batch, gr, g_is64, N_GRAPHS) : 0;
    }
    int rg = t >> 2, cg = t & 3;
    int r0 = rg, r1 = rg + 64;
    unsigned long long acc0[8] = {0, 0, 0, 0, 0, 0, 0, 0};
    unsigned long long acc1[8] = {0, 0, 0, 0, 0, 0, 0, 0};

    for (int h = 0; h < 6; h++) {
        int c = h >> 1;
        __syncthreads();
        if ((h & 1) == 0) {
            for (int i = t; i < 2048; i += 256) {
                int rr = i >> 4, c4 = i & 15;
                int gr = rowBase + rr;
                float4 v = make_float4(0.f, 0.f, 0.f, 0.f);
                if (gr < N_NODES) {
                    if (c == 0) {
                        v = reinterpret_cast<const float4*>(x)[gr * 16 + c4];
                    } else if (c == 1) {
                        v = reinterpret_cast<const float4*>(g_sums)[gr * 16 + c4];
                        float inv = 1.0f / fmaxf(g_cnt[gr], 1.0f);
                        v.x *= inv; v.y *= inv; v.z *= inv; v.w *= inv;
                    } else {
                        v = reinterpret_cast<const float4*>(ga)[batch_s[rr] * 16 + c4];
                    }
                }
                *reinterpret_cast<float4*>(&in_s[rr][c4 * 4]) = v;
            }
        }
        for (int i = t; i < 512; i += 256)
            reinterpret_cast<float4*>(W_s)[i] =
                reinterpret_cast<const float4*>(W1 + h * 2048)[i];
        __syncthreads();
        mma_chunk(in_s, W_s, r0, r1, cg, (h & 1) * 32, acc0, acc1);
    }
    __syncthreads();
    epilogue_store_stats(acc0, acc1, b_s, red_s, t, cg,
                         rowBase + r0, rowBase + r1, blockIdx.x & (NREP - 1),
                         out, st);
}

// --------- layers 2/3: BN(prev stats) folded into W on the fly, relu + stats -
__global__ __launch_bounds__(256) void k_layer64(
        const float* __restrict__ in,
        const float* __restrict__ W,      // raw weights [64][64]
        const float* __restrict__ b,      // raw bias
        const float* __restrict__ st,     // prev-layer stats (NREP replicas)
        const float* __restrict__ g,      // prev-layer BN gamma
        const float* __restrict__ bt,     // prev-layer BN beta
        float* __restrict__ out,
        float* __restrict__ st_out) {
    __shared__ __align__(16) float in_s[128][68];
    __shared__ __align__(16) float W_s[32 * 64];
    __shared__ float red_s[8][2][64];
    __shared__ float a_s[64], c_s[64], b_s[64];
    __shared__ float bred[4][64];

    int t = threadIdx.x;
    int rowBase = blockIdx.x * 128;

    // stage 0: BN fold coefficients from prev-layer stats (sum replicas)
    if (t < 64) {
        float sum = 0.f, sumsq = 0.f;
#pragma unroll
        for (int rep = 0; rep < NREP; rep++) {
            sum += st[rep * 128 + t];
            sumsq += st[rep * 128 + 64 + t];
        }
        const float invN = 1.0f / (float)N_NODES;
        float mean = sum * invN;
        float var = sumsq * invN - mean * mean;
        float a = g[t] * rsqrtf(var + BN_EPS);
        a_s[t] = a;
        c_s[t] = bt[t] - mean * a;
    }
    __syncthreads();

    // stage 1: in_s loads + folded-bias partials
    for (int i = t; i < 2048; i += 256) {
        int rr = i >> 4, c4 = i & 15;
        int gr = rowBase + rr;
        float4 v = (gr < N_NODES)
                       ? reinterpret_cast<const float4*>(in)[gr * 16 + c4]
                       : make_float4(0.f, 0.f, 0.f, 0.f);
        *reinterpret_cast<float4*>(&in_s[rr][c4 * 4]) = v;
    }
    {
        int q = t >> 6, col = t & 63;
        float acc = 0.f;
#pragma unroll
        for (int kk = 0; kk < 16; kk++) {
            int k = q * 16 + kk;
            acc += c_s[k] * __ldg(W + k * 64 + col);
        }
        bred[q][col] = acc;
    }
    __syncthreads();
    if (t < 64) b_s[t] = b[t] + bred[0][t] + bred[1][t] + bred[2][t] + bred[3][t];

    int rg = t >> 2, cg = t & 3;
    int r0 = rg, r1 = rg + 64;
    unsigned long long acc0[8] = {0, 0, 0, 0, 0, 0, 0, 0};
    unsigned long long acc1[8] = {0, 0, 0, 0, 0, 0, 0, 0};

    for (int h = 0; h < 2; h++) {
        __syncthreads();
        for (int i = t; i < 512; i += 256) {
            int k = h * 32 + (i >> 4);
            float4 w = reinterpret_cast<const float4*>(W + h * 2048)[i];
            float a = a_s[k];
            w.x *= a; w.y *= a; w.z *= a; w.w *= a;
            reinterpret_cast<float4*>(W_s)[i] = w;
        }
        __syncthreads();
        mma_chunk(in_s, W_s, r0, r1, cg, h * 32, acc0, acc1);
    }
    __syncthreads();
    epilogue_store_stats(acc0, acc1, b_s, red_s, t, cg,
                         rowBase + r0, rowBase + r1, blockIdx.x & (NREP - 1),
                         out, st_out);
}

// -------------- final: BN(stats3) applied as per-column affine ---------------
__global__ __launch_bounds__(256) void k_final(
        const float* __restrict__ h, const float* __restrict__ st,
        const float* __restrict__ g, const float* __restrict__ bt,
        float* __restrict__ out) {
    __shared__ float a_s[64], c_s[64];
    int t = threadIdx.x;
    if (t < 64) {
        float sum = 0.f, sumsq = 0.f;
#pragma unroll
        for (int rep = 0; rep < NREP; rep++) {
            sum += st[rep * 128 + t];
            sumsq += st[rep * 128 + 64 + t];
        }
        const float invN = 1.0f / (float)N_NODES;
        float mean = sum * invN;
        float var = sumsq * invN - mean * mean;
        float a = g[t] * rsqrtf(var + BN_EPS);
        a_s[t] = a;
        c_s[t] = bt[t] - mean * a;
    }
    __syncthreads();
    int i = blockIdx.x * blockDim.x + t;  // float4 index
    if (i >= N_NODES * 16) return;
    int c4 = (i & 15) * 4;
    float4 v = reinterpret_cast<const float4*>(h)[i];
    v.x = v.x * a_s[c4 + 0] + c_s[c4 + 0];
    v.y = v.y * a_s[c4 + 1] + c_s[c4 + 1];
    v.z = v.z * a_s[c4 + 2] + c_s[c4 + 2];
    v.w = v.w * a_s[c4 + 3] + c_s[c4 + 3];
    reinterpret_cast<float4*>(out)[i] = v;
}

// ------------------------- launch -------------------------------------------
extern "C" void kernel_launch(void* const* d_in, const int* in_sizes, int n_in,
                              void* d_out, int out_size) {
    const float* x = (const float*)d_in[0];
    const void* ei = d_in[1];          // int32 or int64 — detected on device
    const float* ea = (const float*)d_in[2];
    const float* ga = (const float*)d_in[3];
    const void* batch = d_in[4];       // int32 or int64 — detected on device
    const float* W1 = (const float*)d_in[5];
    const float* b1 = (const float*)d_in[6];
    const float* W2 = (const float*)d_in[7];
    const float* b2 = (const float*)d_in[8];
    const float* W3 = (const float*)d_in[9];
    const float* b3 = (const float*)d_in[10];
    const float* g1 = (const float*)d_in[11];
    const float* bt1 = (const float*)d_in[12];
    const float* g2 = (const float*)d_in[13];
    const float* bt2 = (const float*)d_in[14];
    const float* g3 = (const float*)d_in[15];
    const float* bt3 = (const float*)d_in[16];
    float* out = (float*)d_out;

    float *pA, *pB, *pStats;
    cudaGetSymbolAddress((void**)&pA, g_bufA);
    cudaGetSymbolAddress((void**)&pB, g_bufB);
    cudaGetSymbolAddress((void**)&pStats, g_stats);

    const int rowBlocks = (N_NODES + 127) / 128;  // 782
    const int L = NREP * 128;                      // stats stride per layer

    // launches 1..3 tiny so k_scatter is launch #4 (the one ncu captures)
    k_zero1<<<6250, 256>>>();
    k_zero2<<<(N_NODES + 255) / 256, 256>>>();
    k_zero3<<<1, 256>>>((const int*)ei);
    k_scatter<<<(N_EDGES * 16) / 256, 256>>>(ei, ea);
    k_layer1<<<rowBlocks, 256>>>(x, ga, batch, W1, b1, pA, pStats);
    k_layer64<<<rowBlocks, 256>>>(pA, W2, b2, pStats, g1, bt1, pB, pStats + L);
    k_layer64<<<rowBlocks, 256>>>(pB, W3, b3, pStats + L, g2, bt2, pA, pStats + 2 * L);
    k_final<<<(N_NODES * 16 + 255) / 256, 256>>>(pA, pStats + 2 * L, g3, bt3, out);
}

// round 13
// speedup vs baseline: 2.6643x; 1.1907x over previous
#include <cuda_runtime.h>
#include <cstdint>

#define N_NODES 100000
#define N_EDGES 1600000
#define N_GRAPHS 512
#define D 64
#define BN_EPS 1e-5f
#define NREP 16   // stats replicas to de-serialize atomics

// ------------------------- device scratch (no allocs allowed) ---------------
__device__ __align__(16) float g_sums[(size_t)N_NODES * D];   // scatter accumulator
__device__ __align__(16) float g_cnt[N_NODES];
__device__ __align__(16) float g_bufA[(size_t)N_NODES * D];
__device__ __align__(16) float g_bufB[(size_t)N_NODES * D];
__device__ float g_stats[3 * NREP * 128];       // [layer][replica][sum64|sumsq64]
__device__ int g_is64;                          // 1 if indices are int64

// ------------------------- helpers ------------------------------------------
__device__ __forceinline__ void ffma2(unsigned long long& d, unsigned long long a,
                                      unsigned long long b) {
    asm("fma.rn.f32x2 %0, %1, %2, %0;" : "+l"(d) : "l"(a), "l"(b));
}
__device__ __forceinline__ unsigned long long pack2(float v) {
    unsigned long long r;
    asm("mov.b64 %0, {%1, %1};" : "=l"(r) : "f"(v));
    return r;
}
__device__ __forceinline__ void unpack2(unsigned long long p, float& lo, float& hi) {
    asm("mov.b64 {%0, %1}, %2;" : "=f"(lo), "=f"(hi) : "l"(p));
}
// Load index i from an array that may be int32 or int64 (flag-selected).
__device__ __forceinline__ int load_idx(const void* p, int i, int is64, int lim) {
    int v;
    if (is64) v = (int)__ldg(reinterpret_cast<const long long*>(p) + i);
    else      v = __ldg(reinterpret_cast<const int*>(p) + i);
    return min(max(v, 0), lim - 1);  // defensive clamp: never fault
}

// --------------- zero scratch (2 launches so k_layer1 = launch #4) -----------
__global__ void k_zero1() {   // g_sums (1.6M float4) + g_cnt (25K float4)
    int i = blockIdx.x * blockDim.x + threadIdx.x;
    reinterpret_cast<float4*>(g_sums)[i] = make_float4(0.f, 0.f, 0.f, 0.f);
    if (i < N_NODES / 4)
        reinterpret_cast<float4*>(g_cnt)[i] = make_float4(0.f, 0.f, 0.f, 0.f);
}
__global__ void k_zero2(const int* __restrict__ ei32) {  // stats + dtype detect
    int t = threadIdx.x;
    for (int i = t; i < 3 * NREP * 128; i += 256) g_stats[i] = 0.f;
    if (t == 0) {
        // int64 data (values < 2^31) -> odd 32-bit words are zero high-words.
        int nz = 0;
        for (int k = 1; k < 64; k += 2) nz |= ei32[k];
        g_is64 = (nz == 0) ? 1 : 0;
    }
}

// ------------------------- edge scatter (segment_sum + counts) ---------------
__global__ void k_scatter(const void* __restrict__ src,
                          const float* __restrict__ ea) {
    int idx = blockIdx.x * blockDim.x + threadIdx.x;  // E*16 threads
    int e = idx >> 4;
    if (e >= N_EDGES) return;
    int q = idx & 15;
    int is64 = g_is64;
    int s = load_idx(src, e, is64, N_NODES);
    float4 v;
    asm("ld.global.nc.v4.f32 {%0,%1,%2,%3}, [%4];"
        : "=f"(v.x), "=f"(v.y), "=f"(v.z), "=f"(v.w)
        : "l"(ea + (size_t)e * D + q * 4));
    float* dst = g_sums + (size_t)s * D + q * 4;
    asm volatile("red.global.add.v4.f32 [%0], {%1,%2,%3,%4};"
                 :: "l"(dst), "f"(v.x), "f"(v.y), "f"(v.z), "f"(v.w) : "memory");
    if (q == 0)
        asm volatile("red.global.add.f32 [%0], %1;"
                     :: "l"(g_cnt + s), "f"(1.0f) : "memory");
}

// ------------- GEMM inner chunk: 8 rows x 8 cols per thread, 32 k-steps ------
// rows: rg + 16j (j=0..7), cols: cg*4..+3 and cg*4+32..+35.
__device__ __forceinline__ void mma_chunk(
    const float (*in_s)[68], const float* W_s, int rg, int cg, int kb,
    unsigned long long acc[8][4]) {
#pragma unroll
    for (int kk = 0; kk < 32; kk++) {
        const ulonglong2* wrow = reinterpret_cast<const ulonglong2*>(W_s + kk * 64);
        ulonglong2 wa = wrow[cg], wb = wrow[cg + 8];
#pragma unroll
        for (int j = 0; j < 8; j++) {
            unsigned long long ra = pack2(in_s[rg + 16 * j][kb + kk]);
            ffma2(acc[j][0], ra, wa.x); ffma2(acc[j][1], ra, wa.y);
            ffma2(acc[j][2], ra, wb.x); ffma2(acc[j][3], ra, wb.y);
        }
    }
}

// =============== epilogue: bias + relu + store + block stats =================
__device__ __forceinline__ void epilogue(
    unsigned long long acc[8][4], const float* b_s, float (*red_s)[2][64],
    int t, int rg, int cg, int rowBase, int rep,
    float* __restrict__ out, float* __restrict__ st) {
    int c0 = cg * 4;
    float s[8] = {0, 0, 0, 0, 0, 0, 0, 0};
    float s2[8] = {0, 0, 0, 0, 0, 0, 0, 0};
#pragma unroll
    for (int j = 0; j < 8; j++) {
        float r[8];
        unpack2(acc[j][0], r[0], r[1]); unpack2(acc[j][1], r[2], r[3]);
        unpack2(acc[j][2], r[4], r[5]); unpack2(acc[j][3], r[6], r[7]);
#pragma unroll
        for (int i = 0; i < 4; i++) {
            r[i] = fmaxf(r[i] + b_s[c0 + i], 0.f);
            r[4 + i] = fmaxf(r[4 + i] + b_s[c0 + 32 + i], 0.f);
        }
        int grow = rowBase + rg + 16 * j;
        if (grow < N_NODES) {
            float4* o = reinterpret_cast<float4*>(out + (size_t)grow * D);
            o[cg] = make_float4(r[0], r[1], r[2], r[3]);
            o[cg + 8] = make_float4(r[4], r[5], r[6], r[7]);
#pragma unroll
            for (int i = 0; i < 8; i++) { s[i] += r[i]; s2[i] += r[i] * r[i]; }
        }
    }
    // reduce across the 4 rg-subgroups within the warp (lane bits 3,4)
#pragma unroll
    for (int m = 8; m <= 16; m <<= 1) {
#pragma unroll
        for (int i = 0; i < 8; i++) {
            s[i] += __shfl_xor_sync(0xffffffffu, s[i], m);
            s2[i] += __shfl_xor_sync(0xffffffffu, s2[i], m);
        }
    }
    int warp = t >> 5, lane = t & 31;
    if (lane < 8) {
#pragma unroll
        for (int i = 0; i < 4; i++) {
            red_s[warp][0][lane * 4 + i] = s[i];
            red_s[warp][0][lane * 4 + 32 + i] = s[4 + i];
            red_s[warp][1][lane * 4 + i] = s2[i];
            red_s[warp][1][lane * 4 + 32 + i] = s2[4 + i];
        }
    }
    __syncthreads();
    {
        int which = t >> 6, col = t & 63;  // 128 threads -> which in {0,1}
        float a = red_s[0][which][col] + red_s[1][which][col] +
                  red_s[2][which][col] + red_s[3][which][col];
        atomicAdd(st + rep * 128 + which * 64 + col, a);
    }
}

// ------------------------- layer 1: comb[192] @ W1 + b1, relu + stats --------
__global__ __launch_bounds__(128) void k_layer1(
        const float* __restrict__ x,
        const float* __restrict__ ga,
        const void* __restrict__ batch,
        const float* __restrict__ W1,
        const float* __restrict__ b1,
        float* __restrict__ out,
        float* __restrict__ st) {
    __shared__ __align__(16) float in_s[128][68];
    __shared__ __align__(16) float W_s[32 * 64];
    __shared__ float red_s[4][2][64];
    __shared__ float b_s[64];
    __shared__ int batch_s[128];

    int t = threadIdx.x;
    int rowBase = blockIdx.x * 128;
    if (t < 64) b_s[t] = b1[t];
    {
        int gr = rowBase + t;
        batch_s[t] = (gr < N_NODES) ? load_idx(batch, gr, g_is64, N_GRAPHS) : 0;
    }
    int rg = t >> 3, cg = t & 7;
    unsigned long long acc[8][4] = {};

    for (int h = 0; h < 6; h++) {
        int c = h >> 1;
        __syncthreads();
        if ((h & 1) == 0) {
            for (int i = t; i < 2048; i += 128) {
                int rr = i >> 4, c4 = i & 15;
                int gr = rowBase + rr;
                float4 v = make_float4(0.f, 0.f, 0.f, 0.f);
                if (gr < N_NODES) {
                    if (c == 0) {
                        v = reinterpret_cast<const float4*>(x)[gr * 16 + c4];
                    } else if (c == 1) {
                        v = reinterpret_cast<const float4*>(g_sums)[gr * 16 + c4];
                        float inv = 1.0f / fmaxf(g_cnt[gr], 1.0f);
                        v.x *= inv; v.y *= inv; v.z *= inv; v.w *= inv;
                    } else {
                        v = reinterpret_cast<const float4*>(ga)[batch_s[rr] * 16 + c4];
                    }
                }
                *reinterpret_cast<float4*>(&in_s[rr][c4 * 4]) = v;
            }
        }
        for (int i = t; i < 512; i += 128)
            reinterpret_cast<float4*>(W_s)[i] =
                reinterpret_cast<const float4*>(W1 + h * 2048)[i];
        __syncthreads();
        mma_chunk(in_s, W_s, rg, cg, (h & 1) * 32, acc);
    }
    __syncthreads();
    epilogue(acc, b_s, red_s, t, rg, cg, rowBase, blockIdx.x & (NREP - 1), out, st);
}

// --------- layers 2/3: BN(prev stats) folded into W on the fly, relu + stats -
__global__ __launch_bounds__(128) void k_layer64(
        const float* __restrict__ in,
        const float* __restrict__ W,      // raw weights [64][64]
        const float* __restrict__ b,      // raw bias
        const float* __restrict__ st,     // prev-layer stats (NREP replicas)
        const float* __restrict__ g,      // prev-layer BN gamma
        const float* __restrict__ bt,     // prev-layer BN beta
        float* __restrict__ out,
        float* __restrict__ st_out) {
    __shared__ __align__(16) float in_s[128][68];
    __shared__ __align__(16) float W_s[32 * 64];
    __shared__ float red_s[4][2][64];
    __shared__ float a_s[64], c_s[64], b_s[64];
    __shared__ float bred[2][64];

    int t = threadIdx.x;
    int rowBase = blockIdx.x * 128;

    // stage 0: BN fold coefficients from prev-layer stats (sum replicas)
    if (t < 64) {
        float sum = 0.f, sumsq = 0.f;
#pragma unroll
        for (int rep = 0; rep < NREP; rep++) {
            sum += st[rep * 128 + t];
            sumsq += st[rep * 128 + 64 + t];
        }
        const float invN = 1.0f / (float)N_NODES;
        float mean = sum * invN;
        float var = sumsq * invN - mean * mean;
        float a = g[t] * rsqrtf(var + BN_EPS);
        a_s[t] = a;
        c_s[t] = bt[t] - mean * a;
    }
    __syncthreads();

    // stage 1: in_s loads + folded-bias partials
    for (int i = t; i < 2048; i += 128) {
        int rr = i >> 4, c4 = i & 15;
        int gr = rowBase + rr;
        float4 v = (gr < N_NODES)
                       ? reinterpret_cast<const float4*>(in)[gr * 16 + c4]
                       : make_float4(0.f, 0.f, 0.f, 0.f);
        *reinterpret_cast<float4*>(&in_s[rr][c4 * 4]) = v;
    }
    {
        int q = t >> 6, col = t & 63;
        float acc = 0.f;
#pragma unroll
        for (int kk = 0; kk < 32; kk++) {
            int k = q * 32 + kk;
            acc += c_s[k] * __ldg(W + k * 64 + col);
        }
        bred[q][col] = acc;
    }
    __syncthreads();
    if (t < 64) b_s[t] = b[t] + bred[0][t] + bred[1][t];

    int rg = t >> 3, cg = t & 7;
    unsigned long long acc[8][4] = {};

    for (int h = 0; h < 2; h++) {
        __syncthreads();
        for (int i = t; i < 512; i += 128) {
            int k = h * 32 + (i >> 4);
            float4 w = reinterpret_cast<const float4*>(W + h * 2048)[i];
            float a = a_s[k];
            w.x *= a; w.y *= a; w.z *= a; w.w *= a;
            reinterpret_cast<float4*>(W_s)[i] = w;
        }
        __syncthreads();
        mma_chunk(in_s, W_s, rg, cg, h * 32, acc);
    }
    __syncthreads();
    epilogue(acc, b_s, red_s, t, rg, cg, rowBase, blockIdx.x & (NREP - 1),
             out, st_out);
}

// -------------- final: BN(stats3) applied as per-column affine ---------------
__global__ __launch_bounds__(256) void k_final(
        const float* __restrict__ h, const float* __restrict__ st,
        const float* __restrict__ g, const float* __restrict__ bt,
        float* __restrict__ out) {
    __shared__ float a_s[64], c_s[64];
    int t = threadIdx.x;
    if (t < 64) {
        float sum = 0.f, sumsq = 0.f;
#pragma unroll
        for (int rep = 0; rep < NREP; rep++) {
            sum += st[rep * 128 + t];
            sumsq += st[rep * 128 + 64 + t];
        }
        const float invN = 1.0f / (float)N_NODES;
        float mean = sum * invN;
        float var = sumsq * invN - mean * mean;
        float a = g[t] * rsqrtf(var + BN_EPS);
        a_s[t] = a;
        c_s[t] = bt[t] - mean * a;
    }
    __syncthreads();
    int i = blockIdx.x * blockDim.x + t;  // float4 index
    if (i >= N_NODES * 16) return;
    int c4 = (i & 15) * 4;
    float4 v = reinterpret_cast<const float4*>(h)[i];
    v.x = v.x * a_s[c4 + 0] + c_s[c4 + 0];
    v.y = v.y * a_s[c4 + 1] + c_s[c4 + 1];
    v.z = v.z * a_s[c4 + 2] + c_s[c4 + 2];
    v.w = v.w * a_s[c4 + 3] + c_s[c4 + 3];
    reinterpret_cast<float4*>(out)[i] = v;
}

// ------------------------- launch -------------------------------------------
extern "C" void kernel_launch(void* const* d_in, const int* in_sizes, int n_in,
                              void* d_out, int out_size) {
    const float* x = (const float*)d_in[0];
    const void* ei = d_in[1];          // int32 or int64 — detected on device
    const float* ea = (const float*)d_in[2];
    const float* ga = (const float*)d_in[3];
    const void* batch = d_in[4];       // int32 or int64 — detected on device
    const float* W1 = (const float*)d_in[5];
    const float* b1 = (const float*)d_in[6];
    const float* W2 = (const float*)d_in[7];
    const float* b2 = (const float*)d_in[8];
    const float* W3 = (const float*)d_in[9];
    const float* b3 = (const float*)d_in[10];
    const float* g1 = (const float*)d_in[11];
    const float* bt1 = (const float*)d_in[12];
    const float* g2 = (const float*)d_in[13];
    const float* bt2 = (const float*)d_in[14];
    const float* g3 = (const float*)d_in[15];
    const float* bt3 = (const float*)d_in[16];
    float* out = (float*)d_out;

    float *pA, *pB, *pStats;
    cudaGetSymbolAddress((void**)&pA, g_bufA);
    cudaGetSymbolAddress((void**)&pB, g_bufB);
    cudaGetSymbolAddress((void**)&pStats, g_stats);

    const int rowBlocks = (N_NODES + 127) / 128;  // 782
    const int L = NREP * 128;                      // stats stride per layer

    // launch order: k_layer1 is launch #4 (the one ncu -s 5 -c 1 captures)
    k_zero1<<<6250, 256>>>();
    k_zero2<<<1, 256>>>((const int*)ei);
    k_scatter<<<(N_EDGES * 16) / 256, 256>>>(ei, ea);
    k_layer1<<<rowBlocks, 128>>>(x, ga, batch, W1, b1, pA, pStats);
    k_layer64<<<rowBlocks, 128>>>(pA, W2, b2, pStats, g1, bt1, pB, pStats + L);
    k_layer64<<<rowBlocks, 128>>>(pB, W3, b3, pStats + L, g2, bt2, pA, pStats + 2 * L);
    k_final<<<(N_NODES * 16 + 255) / 256, 256>>>(pA, pStats + 2 * L, g3, bt3, out);
}